// round 8
// baseline (speedup 1.0000x reference)
#include <cuda_runtime.h>
#include <cuda_bf16.h>
#include <cstdint>

// Problem constants (fixed by the reference: B=2048, C=16, H=32, W=32 -> F=16384)
#define B_SAMPLES   2048
#define F_FEATS     16384
#define THREADS     256
#define STAGES      3
#define CHUNK_FL    1024                    // floats per chunk per tensor (4 KB)
#define NCHUNKS     (F_FEATS / CHUNK_FL)    // 16
#define CHUNK_BYTES (CHUNK_FL * 4)          // 4096

// Scratch (no device allocation allowed).
__device__ float        g_per_sample[B_SAMPLES];
__device__ unsigned int g_arrive_count = 0;

// ---- inline PTX helpers (self-contained) -----------------------------------
__device__ __forceinline__ uint32_t smem_u32(const void* p) {
    uint32_t a;
    asm("{ .reg .u64 t; cvta.to.shared.u64 t, %1; cvt.u32.u64 %0, t; }"
        : "=r"(a) : "l"(p));
    return a;
}
__device__ __forceinline__ void mbar_init(uint32_t a, uint32_t cnt) {
    asm volatile("mbarrier.init.shared.b64 [%0], %1;" :: "r"(a), "r"(cnt) : "memory");
}
__device__ __forceinline__ void mbar_expect_tx(uint32_t a, uint32_t bytes) {
    asm volatile("mbarrier.arrive.expect_tx.shared.b64 _, [%0], %1;"
                 :: "r"(a), "r"(bytes) : "memory");
}
__device__ __forceinline__ void mbar_arrive(uint32_t a) {
    asm volatile("mbarrier.arrive.shared.b64 _, [%0];" :: "r"(a) : "memory");
}
__device__ __forceinline__ void mbar_wait(uint32_t a, uint32_t parity) {
    asm volatile(
        "{\n\t"
        ".reg .pred P;\n\t"
        "LW_%=:\n\t"
        "mbarrier.try_wait.parity.acquire.cta.shared::cta.b64 P, [%0], %1, 0x989680;\n\t"
        "@P bra.uni LD_%=;\n\t"
        "bra.uni LW_%=;\n\t"
        "LD_%=:\n\t"
        "}" :: "r"(a), "r"(parity) : "memory");
}
__device__ __forceinline__ void bulk_g2s(uint32_t dst, const void* src,
                                         uint32_t bytes, uint32_t mbar) {
    asm volatile(
        "cp.async.bulk.shared::cluster.global.mbarrier::complete_tx::bytes "
        "[%0], [%1], %2, [%3];"
        :: "r"(dst), "l"(src), "r"(bytes), "r"(mbar) : "memory");
}
// -----------------------------------------------------------------------------

__global__ __launch_bounds__(THREADS, 8)
void fnmse_bulk_kernel(const float* __restrict__ out,
                       const float* __restrict__ tgt,
                       const float* __restrict__ fw,
                       float* __restrict__ d_out)
{
    const int b    = blockIdx.x;
    const int tid  = threadIdx.x;
    const int lane = tid & 31;
    const int wid  = tid >> 5;

    __shared__ __align__(16) float sm_o[STAGES][CHUNK_FL];
    __shared__ __align__(16) float sm_t[STAGES][CHUNK_FL];
    __shared__ __align__(8)  unsigned long long mb_full[STAGES];
    __shared__ __align__(8)  unsigned long long mb_empty[STAGES];
    __shared__ float s_ssq[THREADS / 32];
    __shared__ float s_cnt[THREADS / 32];

    const float* o_row = out + (size_t)b * F_FEATS;
    const float* t_row = tgt + (size_t)b * F_FEATS;
    const float4* __restrict__ w4 = reinterpret_cast<const float4*>(fw);

    uint32_t full_a[STAGES], empty_a[STAGES], smo_a[STAGES], smt_a[STAGES];
#pragma unroll
    for (int s = 0; s < STAGES; ++s) {
        full_a[s]  = smem_u32(&mb_full[s]);
        empty_a[s] = smem_u32(&mb_empty[s]);
        smo_a[s]   = smem_u32(&sm_o[s][0]);
        smt_a[s]   = smem_u32(&sm_t[s][0]);
    }

    if (tid == 0) {
#pragma unroll
        for (int s = 0; s < STAGES; ++s) {
            mbar_init(full_a[s], 1);          // producer's expect_tx arrival
            mbar_init(empty_a[s], THREADS);   // all consumers arrive
        }
    }
    __syncthreads();

    // Prologue: issue first STAGES chunks.
    if (tid == 0) {
#pragma unroll
        for (int s = 0; s < STAGES; ++s) {
            mbar_expect_tx(full_a[s], 2 * CHUNK_BYTES);
            bulk_g2s(smo_a[s], o_row + s * CHUNK_FL, CHUNK_BYTES, full_a[s]);
            bulk_g2s(smt_a[s], t_row + s * CHUNK_FL, CHUNK_BYTES, full_a[s]);
        }
    }

    float ssq = 0.0f;
    float cnt = 0.0f;

#pragma unroll
    for (int i = 0; i < NCHUNKS; ++i) {
        const int s = i % STAGES;
        const uint32_t pf = (i / STAGES) & 1;

        mbar_wait(full_a[s], pf);

        // Consume: one float4 of o and t per thread (same feature mapping as
        // the LDG version: feature = i*1024 + tid*4 -> identical sum order).
        float4 o = *reinterpret_cast<const float4*>(&sm_o[s][tid * 4]);
        float4 t = *reinterpret_cast<const float4*>(&sm_t[s][tid * 4]);
        float4 w = w4[i * THREADS + tid];

        {
            bool  m = (t.x == t.x);
            float r = m ? (t.x - o.x) : 0.0f;
            float v = r * w.x;
            ssq = fmaf(v, v, ssq); cnt += m ? 1.0f : 0.0f;
        }
        {
            bool  m = (t.y == t.y);
            float r = m ? (t.y - o.y) : 0.0f;
            float v = r * w.y;
            ssq = fmaf(v, v, ssq); cnt += m ? 1.0f : 0.0f;
        }
        {
            bool  m = (t.z == t.z);
            float r = m ? (t.z - o.z) : 0.0f;
            float v = r * w.z;
            ssq = fmaf(v, v, ssq); cnt += m ? 1.0f : 0.0f;
        }
        {
            bool  m = (t.w == t.w);
            float r = m ? (t.w - o.w) : 0.0f;
            float v = r * w.w;
            ssq = fmaf(v, v, ssq); cnt += m ? 1.0f : 0.0f;
        }

        // Free the slot.
        mbar_arrive(empty_a[s]);

        // Producer refills the slot with chunk i+STAGES.
        if (i + STAGES < NCHUNKS && tid == 0) {
            mbar_wait(empty_a[s], (i / STAGES) & 1);
            mbar_expect_tx(full_a[s], 2 * CHUNK_BYTES);
            bulk_g2s(smo_a[s], o_row + (i + STAGES) * CHUNK_FL, CHUNK_BYTES, full_a[s]);
            bulk_g2s(smt_a[s], t_row + (i + STAGES) * CHUNK_FL, CHUNK_BYTES, full_a[s]);
        }
    }

    // Block reduction (identical to R4).
#pragma unroll
    for (int off = 16; off > 0; off >>= 1) {
        ssq += __shfl_down_sync(0xFFFFFFFFu, ssq, off);
        cnt += __shfl_down_sync(0xFFFFFFFFu, cnt, off);
    }
    if (lane == 0) { s_ssq[wid] = ssq; s_cnt[wid] = cnt; }
    __syncthreads();

    if (wid != 0) return;   // warps 1..7 retire

    float vs = (lane < THREADS / 32) ? s_ssq[lane] : 0.0f;
    float vc = (lane < THREADS / 32) ? s_cnt[lane] : 0.0f;
#pragma unroll
    for (int off = 4; off > 0; off >>= 1) {
        vs += __shfl_down_sync(0xFFFFFFFFu, vs, off);
        vc += __shfl_down_sync(0xFFFFFFFFu, vc, off);
    }

    int is_last = 0;
    if (lane == 0) {
        g_per_sample[b] = vs / vc;
        unsigned int prev;
        asm volatile("atom.add.acq_rel.gpu.global.u32 %0, [%1], 1;"
                     : "=r"(prev) : "l"(&g_arrive_count) : "memory");
        is_last = (prev == (unsigned int)(gridDim.x - 1));
    }
    is_last = __shfl_sync(0xFFFFFFFFu, is_last, 0);

    // Last block: fixed-order deterministic combine (L2-hot, warp 0 only).
    if (is_last) {
        const float4* p4 = reinterpret_cast<const float4*>(g_per_sample);
        float s = 0.0f;
#pragma unroll
        for (int r = 0; r < B_SAMPLES / 4 / 32; ++r) {
            float4 a = p4[r * 32 + lane];
            s += (a.x + a.y) + (a.z + a.w);
        }
#pragma unroll
        for (int off = 16; off > 0; off >>= 1)
            s += __shfl_down_sync(0xFFFFFFFFu, s, off);
        if (lane == 0) {
            d_out[0] = s;
            g_arrive_count = 0u;   // reset for next graph replay
        }
    }
}

extern "C" void kernel_launch(void* const* d_in, const int* in_sizes, int n_in,
                              void* d_out, int out_size)
{
    // metadata order: output, target, e_exp, sample_weight, feature_weight
    const float* out = (const float*)d_in[0];
    const float* tgt = (const float*)d_in[1];
    // d_in[2] (e_exp) and d_in[3] (sample_weight) are unused by the reference.
    const float* fw  = (const float*)d_in[4];

    fnmse_bulk_kernel<<<B_SAMPLES, THREADS>>>(out, tgt, fw, (float*)d_out);
}

// round 9
// speedup vs baseline: 1.0059x; 1.0059x over previous
#include <cuda_runtime.h>
#include <cuda_bf16.h>

// Problem constants (fixed by the reference: B=2048, C=16, H=32, W=32 -> F=16384)
#define B_SAMPLES 2048
#define F_FEATS   16384
#define THREADS   256
#define ROWS_PER_CTA 2
#define NBLOCKS   (B_SAMPLES / ROWS_PER_CTA)   // 1024 -> single wave (<=1184 slots)

// Scratch (no device allocation allowed).
__device__ float        g_per_sample[B_SAMPLES];
__device__ unsigned int g_arrive_count = 0;   // reset by the last block each run

__global__ __launch_bounds__(THREADS, 8)
void fnmse_fused_kernel(const float* __restrict__ out,
                        const float* __restrict__ tgt,
                        const float* __restrict__ fw,
                        float* __restrict__ d_out)
{
    const int b0   = blockIdx.x * ROWS_PER_CTA;   // first of two rows
    const int tid  = threadIdx.x;
    const int lane = tid & 31;
    const int wid  = tid >> 5;

    const float4* __restrict__ oA = reinterpret_cast<const float4*>(out + (size_t)b0 * F_FEATS);
    const float4* __restrict__ tA = reinterpret_cast<const float4*>(tgt + (size_t)b0 * F_FEATS);
    const float4* __restrict__ oB = reinterpret_cast<const float4*>(out + (size_t)(b0 + 1) * F_FEATS);
    const float4* __restrict__ tB = reinterpret_cast<const float4*>(tgt + (size_t)(b0 + 1) * F_FEATS);
    const float4* __restrict__ w4 = reinterpret_cast<const float4*>(fw);

    float ssqA = 0.0f, cntA = 0.0f;
    float ssqB = 0.0f, cntB = 0.0f;

    // Proven loop shape (R1/R4): 16 fully unrolled iterations of plain
    // LDG.128 per row. Both rows processed with independent accumulators so
    // the compiler can interleave/overlap their load streams.
#pragma unroll
    for (int it = 0; it < (F_FEATS / 4) / THREADS; ++it) {
        const int i = it * THREADS + tid;
        float4 w = w4[i];

        float4 o = oA[i];
        float4 t = tA[i];
        {
            bool  m = (t.x == t.x);
            float r = m ? (t.x - o.x) : 0.0f;
            float s = r * w.x;
            ssqA = fmaf(s, s, ssqA); cntA += m ? 1.0f : 0.0f;
        }
        {
            bool  m = (t.y == t.y);
            float r = m ? (t.y - o.y) : 0.0f;
            float s = r * w.y;
            ssqA = fmaf(s, s, ssqA); cntA += m ? 1.0f : 0.0f;
        }
        {
            bool  m = (t.z == t.z);
            float r = m ? (t.z - o.z) : 0.0f;
            float s = r * w.z;
            ssqA = fmaf(s, s, ssqA); cntA += m ? 1.0f : 0.0f;
        }
        {
            bool  m = (t.w == t.w);
            float r = m ? (t.w - o.w) : 0.0f;
            float s = r * w.w;
            ssqA = fmaf(s, s, ssqA); cntA += m ? 1.0f : 0.0f;
        }

        float4 o2 = oB[i];
        float4 t2 = tB[i];
        {
            bool  m = (t2.x == t2.x);
            float r = m ? (t2.x - o2.x) : 0.0f;
            float s = r * w.x;
            ssqB = fmaf(s, s, ssqB); cntB += m ? 1.0f : 0.0f;
        }
        {
            bool  m = (t2.y == t2.y);
            float r = m ? (t2.y - o2.y) : 0.0f;
            float s = r * w.y;
            ssqB = fmaf(s, s, ssqB); cntB += m ? 1.0f : 0.0f;
        }
        {
            bool  m = (t2.z == t2.z);
            float r = m ? (t2.z - o2.z) : 0.0f;
            float s = r * w.z;
            ssqB = fmaf(s, s, ssqB); cntB += m ? 1.0f : 0.0f;
        }
        {
            bool  m = (t2.w == t2.w);
            float r = m ? (t2.w - o2.w) : 0.0f;
            float s = r * w.w;
            ssqB = fmaf(s, s, ssqB); cntB += m ? 1.0f : 0.0f;
        }
    }

    // Warp reduction (both rows).
#pragma unroll
    for (int off = 16; off > 0; off >>= 1) {
        ssqA += __shfl_down_sync(0xFFFFFFFFu, ssqA, off);
        cntA += __shfl_down_sync(0xFFFFFFFFu, cntA, off);
        ssqB += __shfl_down_sync(0xFFFFFFFFu, ssqB, off);
        cntB += __shfl_down_sync(0xFFFFFFFFu, cntB, off);
    }

    __shared__ float4 s_acc[THREADS / 32];
    if (lane == 0) s_acc[wid] = make_float4(ssqA, cntA, ssqB, cntB);
    __syncthreads();

    // Warps 1..7 retire immediately.
    if (wid != 0) return;

    float4 v = (lane < THREADS / 32) ? s_acc[lane]
                                     : make_float4(0.f, 0.f, 0.f, 0.f);
#pragma unroll
    for (int off = 4; off > 0; off >>= 1) {
        v.x += __shfl_down_sync(0xFFFFFFFFu, v.x, off);
        v.y += __shfl_down_sync(0xFFFFFFFFu, v.y, off);
        v.z += __shfl_down_sync(0xFFFFFFFFu, v.z, off);
        v.w += __shfl_down_sync(0xFFFFFFFFu, v.w, off);
    }

    int is_last = 0;
    if (lane == 0) {
        // Deposit both per-sample values (one STG.64), then release-arrive.
        *reinterpret_cast<float2*>(&g_per_sample[b0]) =
            make_float2(v.x / v.y, v.z / v.w);
        unsigned int prev;
        asm volatile("atom.add.acq_rel.gpu.global.u32 %0, [%1], 1;"
                     : "=r"(prev) : "l"(&g_arrive_count) : "memory");
        is_last = (prev == (unsigned int)(NBLOCKS - 1));
    }
    is_last = __shfl_sync(0xFFFFFFFFu, is_last, 0);

    // Last-arriving block: warp 0 alone, fixed-order deterministic combine
    // (8KB, L2-resident, 16 float4 loads per lane).
    if (is_last) {
        const float4* p4 = reinterpret_cast<const float4*>(g_per_sample);
        float s = 0.0f;
#pragma unroll
        for (int r = 0; r < B_SAMPLES / 4 / 32; ++r) {
            float4 a = p4[r * 32 + lane];
            s += (a.x + a.y) + (a.z + a.w);
        }
#pragma unroll
        for (int off = 16; off > 0; off >>= 1)
            s += __shfl_down_sync(0xFFFFFFFFu, s, off);
        if (lane == 0) {
            d_out[0] = s;
            g_arrive_count = 0u;   // reset for next graph replay
        }
    }
}

extern "C" void kernel_launch(void* const* d_in, const int* in_sizes, int n_in,
                              void* d_out, int out_size)
{
    // metadata order: output, target, e_exp, sample_weight, feature_weight
    const float* out = (const float*)d_in[0];
    const float* tgt = (const float*)d_in[1];
    // d_in[2] (e_exp) and d_in[3] (sample_weight) are unused by the reference.
    const float* fw  = (const float*)d_in[4];

    fnmse_fused_kernel<<<NBLOCKS, THREADS>>>(out, tgt, fw, (float*)d_out);
}

// round 10
// speedup vs baseline: 1.0689x; 1.0626x over previous
#include <cuda_runtime.h>
#include <cuda_bf16.h>

// Problem constants (fixed by the reference: B=2048, C=16, H=32, W=32 -> F=16384)
#define B_SAMPLES 2048
#define F_FEATS   16384
#define THREADS   256

// Scratch (no device allocation allowed).
__device__ float        g_per_sample[B_SAMPLES];
__device__ unsigned int g_arrive_count = 0;   // reset by the last block each run

__global__ __launch_bounds__(THREADS, 8)
void fnmse_fused_kernel(const float* __restrict__ out,
                        const float* __restrict__ tgt,
                        const float* __restrict__ fw,
                        float* __restrict__ d_out)
{
    const int b   = blockIdx.x;
    const int tid = threadIdx.x;

    const float4* __restrict__ o4 = reinterpret_cast<const float4*>(out + (size_t)b * F_FEATS);
    const float4* __restrict__ t4 = reinterpret_cast<const float4*>(tgt + (size_t)b * F_FEATS);
    const float4* __restrict__ w4 = reinterpret_cast<const float4*>(fw);

    float ssq = 0.0f;
    float cnt = 0.0f;

    // R4's proven loop (2048 CTAs x 256 thr, 16 unrolled iters) with ONE change:
    //  - o/t use __ldcg (L2-only): streaming data, zero reuse -> don't allocate
    //    L1 lines, don't evict fw.
    //  - fw uses __ldca (L1-allocate): 64KB vector becomes L1-resident per SM,
    //    removing ~2.9 TB/s of redundant L2-hit traffic from the LTS crossbar.
#pragma unroll
    for (int it = 0; it < (F_FEATS / 4) / THREADS; ++it) {
        const int i = it * THREADS + tid;
        float4 o = __ldcg(&o4[i]);
        float4 t = __ldcg(&t4[i]);
        float4 w = __ldca(&w4[i]);

        {
            bool  m = (t.x == t.x);          // !isnan
            float r = m ? (t.x - o.x) : 0.0f;
            float s = r * w.x;
            ssq = fmaf(s, s, ssq);
            cnt += m ? 1.0f : 0.0f;
        }
        {
            bool  m = (t.y == t.y);
            float r = m ? (t.y - o.y) : 0.0f;
            float s = r * w.y;
            ssq = fmaf(s, s, ssq);
            cnt += m ? 1.0f : 0.0f;
        }
        {
            bool  m = (t.z == t.z);
            float r = m ? (t.z - o.z) : 0.0f;
            float s = r * w.z;
            ssq = fmaf(s, s, ssq);
            cnt += m ? 1.0f : 0.0f;
        }
        {
            bool  m = (t.w == t.w);
            float r = m ? (t.w - o.w) : 0.0f;
            float s = r * w.w;
            ssq = fmaf(s, s, ssq);
            cnt += m ? 1.0f : 0.0f;
        }
    }

    // Warp reduction
#pragma unroll
    for (int off = 16; off > 0; off >>= 1) {
        ssq += __shfl_down_sync(0xFFFFFFFFu, ssq, off);
        cnt += __shfl_down_sync(0xFFFFFFFFu, cnt, off);
    }

    __shared__ float s_ssq[THREADS / 32];
    __shared__ float s_cnt[THREADS / 32];
    const int lane = tid & 31;
    const int wid  = tid >> 5;
    if (lane == 0) { s_ssq[wid] = ssq; s_cnt[wid] = cnt; }
    __syncthreads();

    // Warps 1..7 retire immediately — no fence, no trailing barrier.
    if (wid != 0) return;

    float vs = (lane < THREADS / 32) ? s_ssq[lane] : 0.0f;
    float vc = (lane < THREADS / 32) ? s_cnt[lane] : 0.0f;
#pragma unroll
    for (int off = 4; off > 0; off >>= 1) {
        vs += __shfl_down_sync(0xFFFFFFFFu, vs, off);
        vc += __shfl_down_sync(0xFFFFFFFFu, vc, off);
    }

    int is_last = 0;
    if (lane == 0) {
        // Deposit the per-sample value, then release-arrive (orders the STG;
        // acq_rel gives the last block acquire semantics for the readback).
        g_per_sample[b] = vs / vc;
        unsigned int prev;
        asm volatile("atom.add.acq_rel.gpu.global.u32 %0, [%1], 1;"
                     : "=r"(prev) : "l"(&g_arrive_count) : "memory");
        is_last = (prev == (unsigned int)(gridDim.x - 1));
    }
    is_last = __shfl_sync(0xFFFFFFFFu, is_last, 0);

    // Last-arriving block: warp 0 alone, fixed-order deterministic combine
    // (8KB, L2-resident, 16 float4 loads per lane).
    if (is_last) {
        const float4* p4 = reinterpret_cast<const float4*>(g_per_sample);
        float s = 0.0f;
#pragma unroll
        for (int r = 0; r < B_SAMPLES / 4 / 32; ++r) {
            float4 a = p4[r * 32 + lane];
            s += (a.x + a.y) + (a.z + a.w);
        }
#pragma unroll
        for (int off = 16; off > 0; off >>= 1)
            s += __shfl_down_sync(0xFFFFFFFFu, s, off);
        if (lane == 0) {
            d_out[0] = s;
            g_arrive_count = 0u;   // reset for next graph replay
        }
    }
}

extern "C" void kernel_launch(void* const* d_in, const int* in_sizes, int n_in,
                              void* d_out, int out_size)
{
    // metadata order: output, target, e_exp, sample_weight, feature_weight
    const float* out = (const float*)d_in[0];
    const float* tgt = (const float*)d_in[1];
    // d_in[2] (e_exp) and d_in[3] (sample_weight) are unused by the reference.
    const float* fw  = (const float*)d_in[4];

    fnmse_fused_kernel<<<B_SAMPLES, THREADS>>>(out, tgt, fw, (float*)d_out);
}